// round 1
// baseline (speedup 1.0000x reference)
#include <cuda_runtime.h>

// ---------------- problem constants (fixed for this problem) ----------------
#define NN   96000      // nodes
#define EE   600000     // edges
#define HH   4          // heads
#define FFd  32         // features per head
#define HFd  128        // H*F
#define FIN  128        // input features
#define EDd  64         // edge feature dim
#define HID  256        // instruction hidden
#define BB   64         // batch
#define MLEc 1500       // max_local_entity
#define TWO_N (2*NN)
#define SBS  1024
#define SNB  ((TWO_N + SBS - 1) / SBS)   // 188

// ---------------- device scratch (static: no runtime allocation) -----------
__device__ float g_proj [(size_t)NN * HFd];   // x @ W_proj          49 MB
__device__ float g_skipb[(size_t)NN * HFd];   // x @ W_skip + bias   49 MB
__device__ float g_ssrc [NN * HH];
__device__ float g_strg [NN * HH];
__device__ float g_p    [(size_t)EE * HH];    // exp(leaky(score))   9.6 MB
__device__ int   g_deg  [TWO_N];
__device__ int   g_offs [TWO_N];
__device__ int   g_cur  [TWO_N];
__device__ int   g_bsum [SNB];
__device__ int   g_bscan[SNB];
__device__ int   g_nbr  [2 * EE];
__device__ int   g_eid  [2 * EE];
__device__ float g_Msrc [BB * HH * FIN];
__device__ float g_Mtrg [BB * HH * FIN];
__device__ float g_Medge[BB * HH * EDd];

// ---------------- K0: zero degree counters ----------------------------------
__global__ void k0_zero() {
    int i = blockIdx.x * blockDim.x + threadIdx.x;
    if (i < TWO_N) g_deg[i] = 0;
}

// ---------------- K1: instruction bridges -> folded score matrices ----------
// Msrc[b,h,d] = sum_f W_proj[d, h*32+f] * a_src[h,f] * (ins@Wsrc + b)[b, h*32+f]
__global__ void k1_precompute(const float* __restrict__ ins,
                              const float* __restrict__ Wsrc, const float* __restrict__ bsrc,
                              const float* __restrict__ Wtrg, const float* __restrict__ btrg,
                              const float* __restrict__ Wei,  const float* __restrict__ bei,
                              const float* __restrict__ asrc, const float* __restrict__ atrg,
                              const float* __restrict__ aedg,
                              const float* __restrict__ Wproj, const float* __restrict__ Wedge)
{
    __shared__ float csrc[HFd], ctrg[HFd], cedg[HFd];
    int b = blockIdx.x;
    int j = threadIdx.x;                 // 128 threads
    const float* ib = ins + b * HID;
    float s1 = bsrc[j], s2 = btrg[j], s3 = bei[j];
    for (int k = 0; k < HID; ++k) {
        float iv = ib[k];
        s1 += iv * Wsrc[k * HFd + j];
        s2 += iv * Wtrg[k * HFd + j];
        s3 += iv * Wei [k * HFd + j];
    }
    csrc[j] = s1 * asrc[j];
    ctrg[j] = s2 * atrg[j];
    cedg[j] = s3 * aedg[j];
    __syncthreads();

    int d = j;
    for (int h = 0; h < HH; ++h) {
        float m1 = 0.f, m2 = 0.f;
        for (int f = 0; f < FFd; ++f) {
            float wp = Wproj[d * HFd + h * FFd + f];
            m1 += wp * csrc[h * FFd + f];
            m2 += wp * ctrg[h * FFd + f];
        }
        g_Msrc[b * HH * FIN + h * FIN + d] = m1;
        g_Mtrg[b * HH * FIN + h * FIN + d] = m2;
        if (d < EDd) {
            float m3 = 0.f;
            for (int f = 0; f < FFd; ++f)
                m3 += Wedge[d * HFd + h * FFd + f] * cedg[h * FFd + f];
            g_Medge[b * HH * EDd + h * EDd + d] = m3;
        }
    }
}

// ---------------- K2: per-node GEMM (proj + skip) + node scores --------------
// 256 threads, tile = 32 nodes x 256 cols ([W_proj | W_skip])
__global__ void __launch_bounds__(256) k2_node(const float* __restrict__ x,
                                               const float* __restrict__ Wp,
                                               const float* __restrict__ Ws,
                                               const float* __restrict__ bias)
{
    __shared__ float xs[32][129];        // padded: conflict-free column reads
    __shared__ float Wsh[16][256];
    int t = threadIdx.x;
    int n0 = blockIdx.x * 32;

    // stage full x tile (32 x 128)
    for (int i = 0; i < 16; ++i) {
        int idx = i * 256 + t;
        xs[idx >> 7][idx & 127] = x[(size_t)(n0 + (idx >> 7)) * FIN + (idx & 127)];
    }

    int tc = t & 31;     // col group: cols tc*8 .. tc*8+7  (warp = fixed tn)
    int tn = t >> 5;     // node group: nodes tn*4 .. tn*4+3

    float acc[4][8];
#pragma unroll
    for (int a = 0; a < 4; ++a)
#pragma unroll
        for (int c = 0; c < 8; ++c) acc[a][c] = 0.f;

    for (int kc = 0; kc < 8; ++kc) {
        __syncthreads();
        int rb = kc * 16;
        for (int i = 0; i < 16; ++i) {
            float v = (t < 128) ? Wp[(rb + i) * HFd + t]
                                : Ws[(rb + i) * HFd + (t - 128)];
            Wsh[i][t] = v;
        }
        __syncthreads();
#pragma unroll
        for (int k = 0; k < 16; ++k) {
            float4 w0 = *(const float4*)&Wsh[k][tc * 8];
            float4 w1 = *(const float4*)&Wsh[k][tc * 8 + 4];
#pragma unroll
            for (int ni = 0; ni < 4; ++ni) {
                float xv = xs[tn * 4 + ni][rb + k];
                acc[ni][0] += xv * w0.x; acc[ni][1] += xv * w0.y;
                acc[ni][2] += xv * w0.z; acc[ni][3] += xv * w0.w;
                acc[ni][4] += xv * w1.x; acc[ni][5] += xv * w1.y;
                acc[ni][6] += xv * w1.z; acc[ni][7] += xv * w1.w;
            }
        }
    }

    if (tc < 16) {                      // proj columns
        int c = tc * 8;
#pragma unroll
        for (int ni = 0; ni < 4; ++ni) {
            int n = n0 + tn * 4 + ni;
            float4 v0 = make_float4(acc[ni][0], acc[ni][1], acc[ni][2], acc[ni][3]);
            float4 v1 = make_float4(acc[ni][4], acc[ni][5], acc[ni][6], acc[ni][7]);
            *(float4*)&g_proj[(size_t)n * HFd + c]     = v0;
            *(float4*)&g_proj[(size_t)n * HFd + c + 4] = v1;
        }
    } else {                            // skip columns (+bias)
        int c = tc * 8 - 128;
        float4 b0 = *(const float4*)&bias[c];
        float4 b1 = *(const float4*)&bias[c + 4];
#pragma unroll
        for (int ni = 0; ni < 4; ++ni) {
            int n = n0 + tn * 4 + ni;
            float4 v0 = make_float4(acc[ni][0] + b0.x, acc[ni][1] + b0.y,
                                    acc[ni][2] + b0.z, acc[ni][3] + b0.w);
            float4 v1 = make_float4(acc[ni][4] + b1.x, acc[ni][5] + b1.y,
                                    acc[ni][6] + b1.z, acc[ni][7] + b1.w);
            *(float4*)&g_skipb[(size_t)n * HFd + c]     = v0;
            *(float4*)&g_skipb[(size_t)n * HFd + c + 4] = v1;
        }
    }

    // phase 2: node scores via folded matrices (xs is untouched)
    int node = t & 31;
    int q = t >> 5;                     // warp-uniform
    int h = q & 3;
    int n = n0 + node;
    int b = n / MLEc;
    const float* Mv = ((q < 4) ? g_Msrc : g_Mtrg) + b * HH * FIN + h * FIN;
    float s = 0.f;
    for (int d = 0; d < FIN; ++d) s += xs[node][d] * Mv[d];
    if (q < 4) g_ssrc[n * 4 + h] = s;
    else       g_strg[n * 4 + h] = s;
}

// ---------------- K3: edge scores + exp + degree histogram -------------------
__global__ void __launch_bounds__(256) k3_edge(const float* __restrict__ edges,
                                               const int* __restrict__ ei,
                                               const int* __restrict__ bids)
{
    __shared__ float es[64][65];
    int t = threadIdx.x;
    int e0 = blockIdx.x * 64;
    for (int i = 0; i < 16; ++i) {
        int idx = i * 256 + t;
        es[idx >> 6][idx & 63] = edges[(size_t)(e0 + (idx >> 6)) * EDd + (idx & 63)];
    }
    __syncthreads();

    int el = t >> 2, h = t & 3;
    int e = e0 + el;
    int b = bids[e];
    const float* Me = &g_Medge[b * HH * EDd + h * EDd];
    float s = 0.f;
    for (int d = 0; d < EDd; ++d) s += es[el][d] * Me[d];

    int sv = ei[e], tv = ei[EE + e];
    s += g_ssrc[sv * 4 + h] + g_strg[tv * 4 + h];
    s = (s > 0.f) ? s : 0.2f * s;                  // leaky relu
    g_p[(size_t)e * 4 + h] = __expf(s);            // global-max shift cancels
    if (h == 0) {
        atomicAdd(&g_deg[sv], 1);
        atomicAdd(&g_deg[NN + tv], 1);
    }
}

// ---------------- K4: exclusive scan of degrees -> CSR offsets ---------------
__global__ void __launch_bounds__(SBS) k4a_scan() {
    __shared__ int sh[SBS];
    int t = threadIdx.x;
    int i = blockIdx.x * SBS + t;
    int v = (i < TWO_N) ? g_deg[i] : 0;
    sh[t] = v;
    __syncthreads();
    for (int off = 1; off < SBS; off <<= 1) {
        int tmp = (t >= off) ? sh[t - off] : 0;
        __syncthreads();
        if (t >= off) sh[t] += tmp;
        __syncthreads();
    }
    if (i < TWO_N) g_offs[i] = sh[t] - v;          // exclusive
    if (t == SBS - 1) g_bsum[blockIdx.x] = sh[t];
}

__global__ void k4b_bscan() {
    if (threadIdx.x == 0) {
        int s = 0;
        for (int i = 0; i < SNB; ++i) { g_bscan[i] = s; s += g_bsum[i]; }
    }
}

__global__ void __launch_bounds__(SBS) k4c_add() {
    int i = blockIdx.x * SBS + threadIdx.x;
    if (i < TWO_N) {
        int o = g_offs[i] + g_bscan[blockIdx.x];
        g_offs[i] = o;
        g_cur[i]  = o;
    }
}

// ---------------- K5: fill CSR (both directions in one buffer) ---------------
__global__ void k5_fill(const int* __restrict__ ei) {
    int e = blockIdx.x * blockDim.x + threadIdx.x;
    if (e >= EE) return;
    int s = ei[e], t = ei[EE + e];
    int p1 = atomicAdd(&g_cur[s], 1);        // node as source: neighbor = target
    g_nbr[p1] = t; g_eid[p1] = e;
    int p2 = atomicAdd(&g_cur[NN + t], 1);   // node as target: neighbor = source
    g_nbr[p2] = s; g_eid[p2] = e;
}

// ---------------- K6: gather-aggregate (softmax-normalized) + fused LN -------
__global__ void __launch_bounds__(256) k6_agg(const float* __restrict__ gamma,
                                              const float* __restrict__ beta,
                                              float* __restrict__ out)
{
    int n = (blockIdx.x * 256 + threadIdx.x) >> 5;   // one warp per node
    if (n >= NN) return;
    int l = threadIdx.x & 31;
    int h = l >> 3;                                  // head owned by this lane

    // src branch: edges where node is the source; gather proj[target]
    float4 aS = make_float4(0.f, 0.f, 0.f, 0.f); float dS = 0.f;
    {
        int st = g_offs[n], cnt = g_deg[n];
        for (int i = 0; i < cnt; ++i) {
            int pos = st + i;
            int v = g_nbr[pos], e = g_eid[pos];
            float w = g_p[(size_t)e * 4 + h];
            float4 pv = *(const float4*)&g_proj[(size_t)v * HFd + l * 4];
            aS.x += pv.x * w; aS.y += pv.y * w; aS.z += pv.z * w; aS.w += pv.w * w;
            dS += w;
        }
    }
    // trg branch
    float4 aT = make_float4(0.f, 0.f, 0.f, 0.f); float dT = 0.f;
    {
        int st = g_offs[NN + n], cnt = g_deg[NN + n];
        for (int i = 0; i < cnt; ++i) {
            int pos = st + i;
            int v = g_nbr[pos], e = g_eid[pos];
            float w = g_p[(size_t)e * 4 + h];
            float4 pv = *(const float4*)&g_proj[(size_t)v * HFd + l * 4];
            aT.x += pv.x * w; aT.y += pv.y * w; aT.z += pv.z * w; aT.w += pv.w * w;
            dT += w;
        }
    }

    float4 sk = *(const float4*)&g_skipb[(size_t)n * HFd + l * 4];
    float iS = (dS > 0.f) ? 1.f / dS : 0.f;
    float iT = (dT > 0.f) ? 1.f / dT : 0.f;
    float4 sv = make_float4(aS.x * iS + sk.x, aS.y * iS + sk.y,
                            aS.z * iS + sk.z, aS.w * iS + sk.w);
    float4 tv = make_float4(aT.x * iT + sk.x, aT.y * iT + sk.y,
                            aT.z * iT + sk.z, aT.w * iT + sk.w);

    // fused LayerNorm over 256 values (8 per lane)
    float sum = sv.x + sv.y + sv.z + sv.w + tv.x + tv.y + tv.z + tv.w;
    float sq  = sv.x*sv.x + sv.y*sv.y + sv.z*sv.z + sv.w*sv.w
              + tv.x*tv.x + tv.y*tv.y + tv.z*tv.z + tv.w*tv.w;
#pragma unroll
    for (int off = 16; off > 0; off >>= 1) {
        sum += __shfl_xor_sync(0xffffffffu, sum, off);
        sq  += __shfl_xor_sync(0xffffffffu, sq,  off);
    }
    float mu  = sum * (1.f / 256.f);
    float var = sq * (1.f / 256.f) - mu * mu;
    float rs  = rsqrtf(var + 1e-5f);

    float4 g0 = *(const float4*)&gamma[l * 4];
    float4 g1 = *(const float4*)&gamma[128 + l * 4];
    float4 b0 = *(const float4*)&beta[l * 4];
    float4 b1 = *(const float4*)&beta[128 + l * 4];

    float4 o0 = make_float4((sv.x - mu) * rs * g0.x + b0.x,
                            (sv.y - mu) * rs * g0.y + b0.y,
                            (sv.z - mu) * rs * g0.z + b0.z,
                            (sv.w - mu) * rs * g0.w + b0.w);
    float4 o1 = make_float4((tv.x - mu) * rs * g1.x + b1.x,
                            (tv.y - mu) * rs * g1.y + b1.y,
                            (tv.z - mu) * rs * g1.z + b1.z,
                            (tv.w - mu) * rs * g1.w + b1.w);
    *(float4*)&out[(size_t)n * 256 + l * 4]       = o0;   // src_feats first
    *(float4*)&out[(size_t)n * 256 + 128 + l * 4] = o1;   // then trg_feats
}

// ---------------- launch ----------------------------------------------------
extern "C" void kernel_launch(void* const* d_in, const int* in_sizes, int n_in,
                              void* d_out, int out_size)
{
    // index 5 may be the scalar max_local_entity; skip it if present
    int o = 0;
    if (n_in >= 21 && in_sizes[5] <= 2) o = 1;

    const float* x     = (const float*)d_in[0];
    const int*   ei    = (const int*)  d_in[1];
    const float* edges = (const float*)d_in[2];
    const float* ins   = (const float*)d_in[3];
    const int*   bids  = (const int*)  d_in[4];
    const float* Wproj = (const float*)d_in[5 + o];
    const float* Wedge = (const float*)d_in[6 + o];
    const float* Wsrc  = (const float*)d_in[7 + o];
    const float* bsrc  = (const float*)d_in[8 + o];
    const float* Wtrg  = (const float*)d_in[9 + o];
    const float* btrg  = (const float*)d_in[10 + o];
    const float* Wei   = (const float*)d_in[11 + o];
    const float* bei   = (const float*)d_in[12 + o];
    const float* asrc  = (const float*)d_in[13 + o];
    const float* atrg  = (const float*)d_in[14 + o];
    const float* aedg  = (const float*)d_in[15 + o];
    const float* bias  = (const float*)d_in[16 + o];
    const float* Wskip = (const float*)d_in[17 + o];
    const float* gamma = (const float*)d_in[18 + o];
    const float* beta  = (const float*)d_in[19 + o];
    float* out = (float*)d_out;

    k0_zero<<<(TWO_N + 255) / 256, 256>>>();
    k1_precompute<<<BB, 128>>>(ins, Wsrc, bsrc, Wtrg, btrg, Wei, bei,
                               asrc, atrg, aedg, Wproj, Wedge);
    k2_node<<<NN / 32, 256>>>(x, Wproj, Wskip, bias);
    k3_edge<<<EE / 64, 256>>>(edges, ei, bids);
    k4a_scan<<<SNB, SBS>>>();
    k4b_bscan<<<1, 32>>>();
    k4c_add<<<SNB, SBS>>>();
    k5_fill<<<(EE + 255) / 256, 256>>>(ei);
    k6_agg<<<(NN * 32) / 256, 256>>>(gamma, beta, out);
    (void)out_size;
}

// round 8
// speedup vs baseline: 1.8078x; 1.8078x over previous
#include <cuda_runtime.h>
#include <cuda_bf16.h>
#include <mma.h>

using namespace nvcuda;

// ---------------- problem constants (fixed for this problem) ----------------
#define NN   96000      // nodes
#define EE   600000     // edges
#define HH   4          // heads
#define FFd  32         // features per head
#define HFd  128        // H*F
#define FIN  128        // input features
#define EDd  64         // edge feature dim
#define HID  256        // instruction hidden
#define BB   64         // batch
#define MLEc 1500       // max_local_entity
#define TWO_N (2*NN)
#define SBS  1024
#define SNB  ((TWO_N + SBS - 1) / SBS)   // 188

// ---------------- device scratch (static: no runtime allocation) -----------
__device__ float g_proj [(size_t)NN * HFd];   // x @ W_proj          49 MB
__device__ float g_skipb[(size_t)NN * HFd];   // x @ W_skip (bias added in k6)
__device__ float g_ssrc [NN * HH];
__device__ float g_strg [NN * HH];
__device__ float g_p    [(size_t)EE * HH];    // exp(leaky(score))   9.6 MB
__device__ int   g_deg  [TWO_N];
__device__ int   g_offs [TWO_N];
__device__ int   g_cur  [TWO_N];
__device__ int   g_bsum [SNB];
__device__ int   g_bscan[SNB];
__device__ int   g_nbr  [2 * EE];
__device__ int   g_eid  [2 * EE];
__device__ float g_Msrc [BB * HH * FIN];
__device__ float g_Mtrg [BB * HH * FIN];
__device__ float g_Medge[BB * HH * EDd];
// edge bucketing by batch id
__device__ int   g_bcnt [BB];
__device__ int   g_boff [BB + 1];
__device__ int   g_bcur [BB];
__device__ int   g_perm [EE];
// bf16-split operands for tensor-core GEMM
__device__ __nv_bfloat16 g_xh[(size_t)NN * FIN];
__device__ __nv_bfloat16 g_xl[(size_t)NN * FIN];
__device__ __nv_bfloat16 g_wh[FIN * 256];     // [Wproj | Wskip] hi
__device__ __nv_bfloat16 g_wl[FIN * 256];     // [Wproj | Wskip] lo

// ---------------- K0: zero counters -----------------------------------------
__global__ void k0_zero() {
    int i = blockIdx.x * blockDim.x + threadIdx.x;
    if (i < TWO_N) g_deg[i] = 0;
    if (i < BB)    g_bcnt[i] = 0;
}

// ---------------- K1: instruction bridges -> folded score matrices ----------
__global__ void k1_precompute(const float* __restrict__ ins,
                              const float* __restrict__ Wsrc, const float* __restrict__ bsrc,
                              const float* __restrict__ Wtrg, const float* __restrict__ btrg,
                              const float* __restrict__ Wei,  const float* __restrict__ bei,
                              const float* __restrict__ asrc, const float* __restrict__ atrg,
                              const float* __restrict__ aedg,
                              const float* __restrict__ Wproj, const float* __restrict__ Wedge)
{
    __shared__ float csrc[HFd], ctrg[HFd], cedg[HFd];
    int b = blockIdx.x;
    int j = threadIdx.x;                 // 128 threads
    const float* ib = ins + b * HID;
    float s1 = bsrc[j], s2 = btrg[j], s3 = bei[j];
    for (int k = 0; k < HID; ++k) {
        float iv = ib[k];
        s1 += iv * Wsrc[k * HFd + j];
        s2 += iv * Wtrg[k * HFd + j];
        s3 += iv * Wei [k * HFd + j];
    }
    csrc[j] = s1 * asrc[j];
    ctrg[j] = s2 * atrg[j];
    cedg[j] = s3 * aedg[j];
    __syncthreads();

    int d = j;
    for (int h = 0; h < HH; ++h) {
        float m1 = 0.f, m2 = 0.f;
        for (int f = 0; f < FFd; ++f) {
            float wp = Wproj[d * HFd + h * FFd + f];
            m1 += wp * csrc[h * FFd + f];
            m2 += wp * ctrg[h * FFd + f];
        }
        g_Msrc[b * HH * FIN + h * FIN + d] = m1;
        g_Mtrg[b * HH * FIN + h * FIN + d] = m2;
        if (d < EDd) {
            float m3 = 0.f;
            for (int f = 0; f < FFd; ++f)
                m3 += Wedge[d * HFd + h * FFd + f] * cedg[h * FFd + f];
            g_Medge[b * HH * EDd + h * EDd + d] = m3;
        }
    }
}

// ---------------- KC: bf16-split conversions ---------------------------------
__global__ void kc_convx(const float* __restrict__ x) {
    size_t i = ((size_t)blockIdx.x * 256 + threadIdx.x) * 4;
    if (i >= (size_t)NN * FIN) return;
    float4 v = *(const float4*)(x + i);
    __nv_bfloat16 hx = __float2bfloat16_rn(v.x);
    __nv_bfloat16 hy = __float2bfloat16_rn(v.y);
    __nv_bfloat16 hz = __float2bfloat16_rn(v.z);
    __nv_bfloat16 hw = __float2bfloat16_rn(v.w);
    g_xh[i]   = hx; g_xh[i+1] = hy; g_xh[i+2] = hz; g_xh[i+3] = hw;
    g_xl[i]   = __float2bfloat16_rn(v.x - __bfloat162float(hx));
    g_xl[i+1] = __float2bfloat16_rn(v.y - __bfloat162float(hy));
    g_xl[i+2] = __float2bfloat16_rn(v.z - __bfloat162float(hz));
    g_xl[i+3] = __float2bfloat16_rn(v.w - __bfloat162float(hw));
}

__global__ void kc_convw(const float* __restrict__ Wp, const float* __restrict__ Ws) {
    int idx = blockIdx.x * 256 + threadIdx.x;   // 0 .. 128*256-1
    if (idx >= FIN * 256) return;
    int r = idx >> 8, c = idx & 255;
    float v = (c < HFd) ? Wp[r * HFd + c] : Ws[r * HFd + (c - HFd)];
    __nv_bfloat16 h = __float2bfloat16_rn(v);
    g_wh[idx] = h;
    g_wl[idx] = __float2bfloat16_rn(v - __bfloat162float(h));
}

// ---------------- K2: tensor-core GEMM (bf16 split, fp32 acc) ----------------
// C[96000 x 256] = x[96000 x 128] @ [Wproj|Wskip][128 x 256]
// block = 64 rows x 64 cols, 8 warps, each warp 16x32 (1 row-frag x 2 col-frags)
__global__ void __launch_bounds__(256) k2_mma() {
    __shared__ __nv_bfloat16 Bh[FIN][72];
    __shared__ __nv_bfloat16 Bl[FIN][72];
    int t = threadIdx.x;
    int n0 = blockIdx.x * 64;
    int c0 = blockIdx.y * 64;

    for (int i = t; i < FIN * 64; i += 256) {
        int r = i >> 6, c = i & 63;
        Bh[r][c] = g_wh[r * 256 + c0 + c];
        Bl[r][c] = g_wl[r * 256 + c0 + c];
    }
    __syncthreads();

    int wid = t >> 5;
    int wr = wid >> 1;              // row tile 0..3
    int wcb = (wid & 1) * 2;        // col-tile base 0 or 2

    wmma::fragment<wmma::accumulator, 16, 16, 16, float> acc[2];
    wmma::fill_fragment(acc[0], 0.0f);
    wmma::fill_fragment(acc[1], 0.0f);

    const __nv_bfloat16* arow_h = g_xh + (size_t)(n0 + wr * 16) * FIN;
    const __nv_bfloat16* arow_l = g_xl + (size_t)(n0 + wr * 16) * FIN;

#pragma unroll
    for (int k = 0; k < FIN / 16; ++k) {
        wmma::fragment<wmma::matrix_a, 16, 16, 16, __nv_bfloat16, wmma::row_major> ah, al;
        wmma::load_matrix_sync(ah, arow_h + k * 16, FIN);
        wmma::load_matrix_sync(al, arow_l + k * 16, FIN);
#pragma unroll
        for (int f = 0; f < 2; ++f) {
            wmma::fragment<wmma::matrix_b, 16, 16, 16, __nv_bfloat16, wmma::row_major> bh, bl;
            wmma::load_matrix_sync(bh, &Bh[k * 16][(wcb + f) * 16], 72);
            wmma::load_matrix_sync(bl, &Bl[k * 16][(wcb + f) * 16], 72);
            wmma::mma_sync(acc[f], ah, bh, acc[f]);
            wmma::mma_sync(acc[f], ah, bl, acc[f]);
            wmma::mma_sync(acc[f], al, bh, acc[f]);
        }
    }

    // destination is block-uniform: c0 < 128 -> proj, else skip (raw, bias in k6)
    float* dstbase = (c0 < HFd) ? g_proj : g_skipb;
    int cbase = (c0 < HFd) ? c0 : (c0 - HFd);
#pragma unroll
    for (int f = 0; f < 2; ++f) {
        int cg = cbase + (wcb + f) * 16;
        wmma::store_matrix_sync(dstbase + (size_t)(n0 + wr * 16) * HFd + cg,
                                acc[f], HFd, wmma::mem_row_major);
    }
}

// ---------------- K2S: node scores via folded matrices -----------------------
__global__ void __launch_bounds__(256) k2s_scores(const float* __restrict__ x) {
    __shared__ float xs[32][129];
    int t = threadIdx.x;
    int n0 = blockIdx.x * 32;
    for (int i = 0; i < 16; ++i) {
        int idx = i * 256 + t;
        xs[idx >> 7][idx & 127] = x[(size_t)(n0 + (idx >> 7)) * FIN + (idx & 127)];
    }
    __syncthreads();

    int node = t & 31;
    int q = t >> 5;                 // warp-uniform
    int h = q & 3;
    int n = n0 + node;
    int b = n / MLEc;
    const float* Mv = ((q < 4) ? g_Msrc : g_Mtrg) + b * HH * FIN + h * FIN;
    float s = 0.f;
    for (int d = 0; d < FIN; ++d) s += xs[node][d] * Mv[d];
    if (q < 4) g_ssrc[n * 4 + h] = s;
    else       g_strg[n * 4 + h] = s;
}

// ---------------- KB: bucket edges by batch id -------------------------------
__global__ void __launch_bounds__(256) kb_hist(const int* __restrict__ bids) {
    __shared__ int h[BB];
    int t = threadIdx.x;
    if (t < BB) h[t] = 0;
    __syncthreads();
    int base = blockIdx.x * 1024;
#pragma unroll
    for (int j = 0; j < 4; ++j) {
        int e = base + j * 256 + t;
        if (e < EE) atomicAdd(&h[bids[e]], 1);
    }
    __syncthreads();
    if (t < BB && h[t]) atomicAdd(&g_bcnt[t], h[t]);
}

__global__ void kb_scan() {
    if (threadIdx.x == 0) {
        int s = 0;
        for (int b = 0; b < BB; ++b) {
            g_boff[b] = s; g_bcur[b] = s; s += g_bcnt[b];
        }
        g_boff[BB] = s;
    }
}

__global__ void __launch_bounds__(256) kb_fill(const int* __restrict__ bids) {
    __shared__ int h[BB], base[BB];
    int t = threadIdx.x;
    if (t < BB) h[t] = 0;
    __syncthreads();
    int e0 = blockIdx.x * 1024;
    int eb[4], rk[4];
#pragma unroll
    for (int j = 0; j < 4; ++j) {
        int e = e0 + j * 256 + t;
        if (e < EE) { eb[j] = bids[e]; rk[j] = atomicAdd(&h[eb[j]], 1); }
        else eb[j] = -1;
    }
    __syncthreads();
    if (t < BB && h[t]) base[t] = atomicAdd(&g_bcur[t], h[t]);
    __syncthreads();
#pragma unroll
    for (int j = 0; j < 4; ++j) {
        if (eb[j] >= 0) g_perm[base[eb[j]] + rk[j]] = e0 + j * 256 + t;
    }
}

// ---------------- K3: edge scores (batch-grouped) + exp + degree histogram ---
__global__ void __launch_bounds__(256) k3_edge(const float* __restrict__ edges,
                                               const int* __restrict__ ei)
{
    __shared__ float Me[HH * EDd];      // 1 KB
    int b = blockIdx.y;
    int t = threadIdx.x;
    Me[t] = g_Medge[b * HH * EDd + t];
    __syncthreads();

    int start = g_boff[b], end = g_boff[b + 1];
    const float4* Me4 = (const float4*)Me;

    for (int pos = start + blockIdx.x * 256 + t; pos < end; pos += gridDim.x * 256) {
        int e = g_perm[pos];
        const float4* er = (const float4*)(edges + (size_t)e * EDd);
        float a0 = 0.f, a1 = 0.f, a2 = 0.f, a3 = 0.f;
#pragma unroll
        for (int i = 0; i < 16; ++i) {
            float4 v  = er[i];
            float4 m0 = Me4[i];
            float4 m1 = Me4[16 + i];
            float4 m2 = Me4[32 + i];
            float4 m3 = Me4[48 + i];
            a0 += v.x * m0.x + v.y * m0.y + v.z * m0.z + v.w * m0.w;
            a1 += v.x * m1.x + v.y * m1.y + v.z * m1.z + v.w * m1.w;
            a2 += v.x * m2.x + v.y * m2.y + v.z * m2.z + v.w * m2.w;
            a3 += v.x * m3.x + v.y * m3.y + v.z * m3.z + v.w * m3.w;
        }
        int sv = ei[e], tv = ei[EE + e];
        float4 ss = *(const float4*)&g_ssrc[sv * 4];
        float4 st = *(const float4*)&g_strg[tv * 4];
        float s0 = a0 + ss.x + st.x;
        float s1 = a1 + ss.y + st.y;
        float s2 = a2 + ss.z + st.z;
        float s3 = a3 + ss.w + st.w;
        s0 = (s0 > 0.f) ? s0 : 0.2f * s0;
        s1 = (s1 > 0.f) ? s1 : 0.2f * s1;
        s2 = (s2 > 0.f) ? s2 : 0.2f * s2;
        s3 = (s3 > 0.f) ? s3 : 0.2f * s3;
        float4 p = make_float4(__expf(s0), __expf(s1), __expf(s2), __expf(s3));
        *(float4*)&g_p[(size_t)e * 4] = p;
        atomicAdd(&g_deg[sv], 1);
        atomicAdd(&g_deg[NN + tv], 1);
    }
}

// ---------------- K4: exclusive scan of degrees -> CSR offsets ---------------
__global__ void __launch_bounds__(SBS) k4a_scan() {
    __shared__ int sh[SBS];
    int t = threadIdx.x;
    int i = blockIdx.x * SBS + t;
    int v = (i < TWO_N) ? g_deg[i] : 0;
    sh[t] = v;
    __syncthreads();
    for (int off = 1; off < SBS; off <<= 1) {
        int tmp = (t >= off) ? sh[t - off] : 0;
        __syncthreads();
        if (t >= off) sh[t] += tmp;
        __syncthreads();
    }
    if (i < TWO_N) g_offs[i] = sh[t] - v;
    if (t == SBS - 1) g_bsum[blockIdx.x] = sh[t];
}

__global__ void k4b_bscan() {
    if (threadIdx.x == 0) {
        int s = 0;
        for (int i = 0; i < SNB; ++i) { g_bscan[i] = s; s += g_bsum[i]; }
    }
}

__global__ void __launch_bounds__(SBS) k4c_add() {
    int i = blockIdx.x * SBS + threadIdx.x;
    if (i < TWO_N) {
        int o = g_offs[i] + g_bscan[blockIdx.x];
        g_offs[i] = o;
        g_cur[i]  = o;
    }
}

// ---------------- K5: fill CSR (both directions in one buffer) ---------------
__global__ void k5_fill(const int* __restrict__ ei) {
    int e = blockIdx.x * blockDim.x + threadIdx.x;
    if (e >= EE) return;
    int s = ei[e], t = ei[EE + e];
    int p1 = atomicAdd(&g_cur[s], 1);
    g_nbr[p1] = t; g_eid[p1] = e;
    int p2 = atomicAdd(&g_cur[NN + t], 1);
    g_nbr[p2] = s; g_eid[p2] = e;
}

// ---------------- K6: gather-aggregate (softmax-normalized) + fused LN -------
__global__ void __launch_bounds__(256) k6_agg(const float* __restrict__ bias,
                                              const float* __restrict__ gamma,
                                              const float* __restrict__ beta,
                                              float* __restrict__ out)
{
    int n = (blockIdx.x * 256 + threadIdx.x) >> 5;
    if (n >= NN) return;
    int l = threadIdx.x & 31;
    int h = l >> 3;

    float4 aS = make_float4(0.f, 0.f, 0.f, 0.f); float dS = 0.f;
    {
        int st = g_offs[n], cnt = g_deg[n];
        for (int i = 0; i < cnt; ++i) {
            int pos = st + i;
            int v = g_nbr[pos], e = g_eid[pos];
            float w = g_p[(size_t)e * 4 + h];
            float4 pv = *(const float4*)&g_proj[(size_t)v * HFd + l * 4];
            aS.x += pv.x * w; aS.y += pv.y * w; aS.z += pv.z * w; aS.w += pv.w * w;
            dS += w;
        }
    }
    float4 aT = make_float4(0.f, 0.f, 0.f, 0.f); float dT = 0.f;
    {
        int st = g_offs[NN + n], cnt = g_deg[NN + n];
        for (int i = 0; i < cnt; ++i) {
            int pos = st + i;
            int v = g_nbr[pos], e = g_eid[pos];
            float w = g_p[(size_t)e * 4 + h];
            float4 pv = *(const float4*)&g_proj[(size_t)v * HFd + l * 4];
            aT.x += pv.x * w; aT.y += pv.y * w; aT.z += pv.z * w; aT.w += pv.w * w;
            dT += w;
        }
    }

    float4 sk = *(const float4*)&g_skipb[(size_t)n * HFd + l * 4];
    float4 bi = *(const float4*)&bias[l * 4];
    sk.x += bi.x; sk.y += bi.y; sk.z += bi.z; sk.w += bi.w;
    float iS = (dS > 0.f) ? 1.f / dS : 0.f;
    float iT = (dT > 0.f) ? 1.f / dT : 0.f;
    float4 sv = make_float4(aS.x * iS + sk.x, aS.y * iS + sk.y,
                            aS.z * iS + sk.z, aS.w * iS + sk.w);
    float4 tv = make_float4(aT.x * iT + sk.x, aT.y * iT + sk.y,
                            aT.z * iT + sk.z, aT.w * iT + sk.w);

    float sum = sv.x + sv.y + sv.z + sv.w + tv.x + tv.y + tv.z + tv.w;
    float sq  = sv.x*sv.x + sv.y*sv.y + sv.z*sv.z + sv.w*sv.w
              + tv.x*tv.x + tv.y*tv.y + tv.z*tv.z + tv.w*tv.w;
#pragma unroll
    for (int off = 16; off > 0; off >>= 1) {
        sum += __shfl_xor_sync(0xffffffffu, sum, off);
        sq  += __shfl_xor_sync(0xffffffffu, sq,  off);
    }
    float mu  = sum * (1.f / 256.f);
    float var = sq * (1.f / 256.f) - mu * mu;
    float rs  = rsqrtf(var + 1e-5f);

    float4 g0 = *(const float4*)&gamma[l * 4];
    float4 g1 = *(const float4*)&gamma[128 + l * 4];
    float4 b0 = *(const float4*)&beta[l * 4];
    float4 b1 = *(const float4*)&beta[128 + l * 4];

    float4 o0 = make_float4((sv.x - mu) * rs * g0.x + b0.x,
                            (sv.y - mu) * rs * g0.y + b0.y,
                            (sv.z - mu) * rs * g0.z + b0.z,
                            (sv.w - mu) * rs * g0.w + b0.w);
    float4 o1 = make_float4((tv.x - mu) * rs * g1.x + b1.x,
                            (tv.y - mu) * rs * g1.y + b1.y,
                            (tv.z - mu) * rs * g1.z + b1.z,
                            (tv.w - mu) * rs * g1.w + b1.w);
    *(float4*)&out[(size_t)n * 256 + l * 4]       = o0;
    *(float4*)&out[(size_t)n * 256 + 128 + l * 4] = o1;
}

// ---------------- launch ----------------------------------------------------
extern "C" void kernel_launch(void* const* d_in, const int* in_sizes, int n_in,
                              void* d_out, int out_size)
{
    int o = 0;
    if (n_in >= 21 && in_sizes[5] <= 2) o = 1;

    const float* x     = (const float*)d_in[0];
    const int*   ei    = (const int*)  d_in[1];
    const float* edges = (const float*)d_in[2];
    const float* ins   = (const float*)d_in[3];
    const int*   bids  = (const int*)  d_in[4];
    const float* Wproj = (const float*)d_in[5 + o];
    const float* Wedge = (const float*)d_in[6 + o];
    const float* Wsrc  = (const float*)d_in[7 + o];
    const float* bsrc  = (const float*)d_in[8 + o];
    const float* Wtrg  = (const float*)d_in[9 + o];
    const float* btrg  = (const float*)d_in[10 + o];
    const float* Wei   = (const float*)d_in[11 + o];
    const float* bei   = (const float*)d_in[12 + o];
    const float* asrc  = (const float*)d_in[13 + o];
    const float* atrg  = (const float*)d_in[14 + o];
    const float* aedg  = (const float*)d_in[15 + o];
    const float* bias  = (const float*)d_in[16 + o];
    const float* Wskip = (const float*)d_in[17 + o];
    const float* gamma = (const float*)d_in[18 + o];
    const float* beta  = (const float*)d_in[19 + o];
    float* out = (float*)d_out;

    k0_zero<<<(TWO_N + 255) / 256, 256>>>();
    k1_precompute<<<BB, 128>>>(ins, Wsrc, bsrc, Wtrg, btrg, Wei, bei,
                               asrc, atrg, aedg, Wproj, Wedge);
    kc_convx<<<(int)(((size_t)NN * FIN / 4 + 255) / 256), 256>>>(x);
    kc_convw<<<(FIN * 256 + 255) / 256, 256>>>(Wproj, Wskip);
    {
        dim3 g2(NN / 64, 4);
        k2_mma<<<g2, 256>>>();
    }
    k2s_scores<<<NN / 32, 256>>>(x);
    kb_hist<<<(EE + 1023) / 1024, 256>>>(bids);
    kb_scan<<<1, 32>>>();
    kb_fill<<<(EE + 1023) / 1024, 256>>>(bids);
    {
        dim3 g3(38, BB);
        k3_edge<<<g3, 256>>>(edges, ei);
    }
    k4a_scan<<<SNB, SBS>>>();
    k4b_bscan<<<1, 32>>>();
    k4c_add<<<SNB, SBS>>>();
    k5_fill<<<(EE + 255) / 256, 256>>>(ei);
    k6_agg<<<(NN * 32) / 256, 256>>>(bias, gamma, beta, out);
    (void)out_size;
}